// round 2
// baseline (speedup 1.0000x reference)
#include <cuda_runtime.h>
#include <cuda_bf16.h>

// StixelLoss fused kernel, H-segmented for occupancy.
// inputs:  (B=256, C=2, H=192, W=256) f32
// targets: (1, B, C, H, W) f32 (same linear layout after squeeze)
// out:     scalar f32 = ALPHA*bce_mean + BETA*cuts + GAMMA*dense

#define HH   192
#define WW   256
#define NBC  512     // B*C blocks
#define NSEG 4
#define SEGH (HH / NSEG)   // 48

__global__ void sx_zero_kernel(float* out) {
    if (threadIdx.x == 0) out[0] = 0.0f;
}

__global__ __launch_bounds__(1024, 2)
void stixel_kernel(const float* __restrict__ inp,
                   const float* __restrict__ tgt,
                   float* __restrict__ out) {
    const int bc = blockIdx.x;             // b*2 + c
    const int c  = bc & 1;
    const int w  = threadIdx.x & (WW - 1); // column
    const int s  = threadIdx.x >> 8;       // h-segment 0..3
    const int h0 = s * SEGH;

    const float* ip = inp + (size_t)bc * (HH * WW) + (size_t)h0 * WW + w;
    const float* tp = tgt + (size_t)bc * (HH * WW) + (size_t)h0 * WW + w;

    float bce   = 0.0f;
    float dense = 0.0f;
    int   cuts  = 0;

    __shared__ int   s_last[NSEG][WW];
    __shared__ float sred[32];

    if (c == 0) {
        // channel 0: BCE + cuts count
        #pragma unroll 4
        for (int i = 0; i < SEGH; ++i) {
            float p = __ldcs(ip + i * WW);
            float t = __ldcs(tp + i * WW);
            float lp  = fmaxf(__logf(p), -100.0f);
            float l1p = fmaxf(__logf(1.0f - p), -100.0f);
            bce += fmaf(t, lp - l1p, l1p);
            cuts += (p > 0.5f) ? 1 : 0;
        }
    } else {
        // channel 1: BCE + segmented dense scan.
        // Encoding: prev==0 means "no visible predecessor" (a hit at global
        // h=0 sets prev=0, which the reference's prev!=0 check also ignores).
        int prev     = 0;
        int firstHit = -1;
        #pragma unroll 4
        for (int i = 0; i < SEGH; ++i) {
            const int h = h0 + i;
            float p = __ldcs(ip + i * WW);
            float t = __ldcs(tp + i * WW);
            float lp  = fmaxf(__logf(p), -100.0f);
            float l1p = fmaxf(__logf(1.0f - p), -100.0f);
            bce += fmaf(t, lp - l1p, l1p);
            bool m = (p > 0.5f) && (h < HH - 1);   // dense loop excludes h=191
            if (m) {
                if (prev != 0) {
                    float d = (float)(h - prev);
                    dense += __fdividef(1.0f, d * d * d);
                }
                if (firstHit < 0) firstHit = h;
                prev = h;
            }
        }
        // publish last hit of this segment (0 = none / invisible)
        s_last[s][w] = prev;
        __syncthreads();
        // stitch: cross-boundary contribution of this segment's first hit
        if (s > 0 && firstHit >= 0) {
            int pg = 0;
            for (int j = s - 1; j >= 0; --j) {
                int lh = s_last[j][w];
                if (lh != 0) { pg = lh; break; }
            }
            if (pg != 0) {
                float d = (float)(firstHit - pg);
                dense += __fdividef(1.0f, d * d * d);
            }
        }
    }

    // combine per-thread terms (ALPHA=1, BETA=0.001, GAMMA=0.1)
    const float INV_N = 1.0f / (float)((size_t)NBC * HH * WW);
    float val = -bce * INV_N + 0.001f * (float)cuts + 0.1f * dense;

    // block reduction over 1024 threads
    #pragma unroll
    for (int off = 16; off > 0; off >>= 1)
        val += __shfl_down_sync(0xffffffffu, val, off);
    int lane = threadIdx.x & 31;
    int wid  = threadIdx.x >> 5;
    if (lane == 0) sred[wid] = val;
    __syncthreads();
    if (wid == 0) {
        val = sred[lane];
        #pragma unroll
        for (int off = 16; off > 0; off >>= 1)
            val += __shfl_down_sync(0xffffffffu, val, off);
        if (lane == 0) atomicAdd(out, val);
    }
}

extern "C" void kernel_launch(void* const* d_in, const int* in_sizes, int n_in,
                              void* d_out, int out_size) {
    const float* inp = (const float*)d_in[0];
    const float* tgt = (const float*)d_in[1];
    float* out = (float*)d_out;

    sx_zero_kernel<<<1, 32>>>(out);
    stixel_kernel<<<NBC, 1024>>>(inp, tgt, out);
}

// round 3
// speedup vs baseline: 1.0551x; 1.0551x over previous
#include <cuda_runtime.h>
#include <cuda_bf16.h>

// StixelLoss fused kernel, float4 loads + H-segmented dense scan.
// inputs:  (B=256, C=2, H=192, W=256) f32
// targets: (1, B, C, H, W) f32 (same linear layout after squeeze)
// out:     scalar f32 = ALPHA*bce_mean + BETA*cuts + GAMMA*dense

#define HH   192
#define WW   256
#define NBC  512            // B*C blocks
#define NSEG 4
#define SEGH (HH / NSEG)    // 48
#define NQ   (WW / 4)       // 64 float4 quads per row

__global__ void sx_zero_kernel(float* out) {
    if (threadIdx.x == 0) out[0] = 0.0f;
}

__global__ __launch_bounds__(256)
void stixel_kernel(const float* __restrict__ inp,
                   const float* __restrict__ tgt,
                   float* __restrict__ out) {
    const int bc = blockIdx.x;            // b*2 + c
    const int c  = bc & 1;
    const int q  = threadIdx.x & (NQ - 1);   // column quad (cols 4q..4q+3)
    const int s  = threadIdx.x >> 6;          // h-segment 0..3
    const int h0 = s * SEGH;

    const size_t base = (size_t)bc * (HH * WW) + (size_t)h0 * WW + 4 * q;
    const float4* ip4 = (const float4*)(inp + base);
    const float4* tp4 = (const float4*)(tgt + base);

    float bce   = 0.0f;
    float dense = 0.0f;
    int   cuts  = 0;

    __shared__ int   s_last[NSEG][WW];
    __shared__ float sred[8];

    if (c == 0) {
        // channel 0: BCE + cuts count
        #pragma unroll 4
        for (int i = 0; i < SEGH; ++i) {
            float4 p = ip4[i * NQ];
            float4 t = tp4[i * NQ];
            const float pv[4] = {p.x, p.y, p.z, p.w};
            const float tv[4] = {t.x, t.y, t.z, t.w};
            #pragma unroll
            for (int j = 0; j < 4; ++j) {
                float lp  = fmaxf(__logf(pv[j]), -100.0f);
                float l1p = fmaxf(__logf(1.0f - pv[j]), -100.0f);
                bce += fmaf(tv[j], lp - l1p, l1p);
                cuts += (pv[j] > 0.5f) ? 1 : 0;
            }
        }
        __syncthreads();   // keep block convergent with channel-1 path
    } else {
        // channel 1: BCE + segmented dense scan over 4 columns.
        // Encoding: prev==0 means "no visible predecessor" (a hit at global
        // h=0 sets prev=0, which the reference's prev!=0 check also ignores).
        int prev[4]     = {0, 0, 0, 0};
        int firstHit[4] = {-1, -1, -1, -1};
        #pragma unroll 4
        for (int i = 0; i < SEGH; ++i) {
            const int h = h0 + i;
            float4 p = ip4[i * NQ];
            float4 t = tp4[i * NQ];
            const float pv[4] = {p.x, p.y, p.z, p.w};
            const float tv[4] = {t.x, t.y, t.z, t.w};
            #pragma unroll
            for (int j = 0; j < 4; ++j) {
                float lp  = fmaxf(__logf(pv[j]), -100.0f);
                float l1p = fmaxf(__logf(1.0f - pv[j]), -100.0f);
                bce += fmaf(tv[j], lp - l1p, l1p);
                bool m = (pv[j] > 0.5f) && (h < HH - 1);  // dense excludes h=191
                if (m) {
                    if (prev[j] != 0) {
                        float d = (float)(h - prev[j]);
                        dense += __fdividef(1.0f, d * d * d);
                    }
                    if (firstHit[j] < 0) firstHit[j] = h;
                    prev[j] = h;
                }
            }
        }
        // publish last hit per column (0 = none / invisible)
        #pragma unroll
        for (int j = 0; j < 4; ++j) s_last[s][4 * q + j] = prev[j];
        __syncthreads();
        // stitch: cross-boundary contribution of this segment's first hits
        if (s > 0) {
            #pragma unroll
            for (int j = 0; j < 4; ++j) {
                if (firstHit[j] >= 0) {
                    int pg = 0;
                    for (int k = s - 1; k >= 0; --k) {
                        int lh = s_last[k][4 * q + j];
                        if (lh != 0) { pg = lh; break; }
                    }
                    if (pg != 0) {
                        float d = (float)(firstHit[j] - pg);
                        dense += __fdividef(1.0f, d * d * d);
                    }
                }
            }
        }
    }

    // combine per-thread terms (ALPHA=1, BETA=0.001, GAMMA=0.1)
    const float INV_N = 1.0f / (float)((size_t)NBC * HH * WW);
    float val = -bce * INV_N + 0.001f * (float)cuts + 0.1f * dense;

    // block reduction over 256 threads
    #pragma unroll
    for (int off = 16; off > 0; off >>= 1)
        val += __shfl_down_sync(0xffffffffu, val, off);
    int lane = threadIdx.x & 31;
    int wid  = threadIdx.x >> 5;
    if (lane == 0) sred[wid] = val;
    __syncthreads();
    if (wid == 0) {
        val = (lane < 8) ? sred[lane] : 0.0f;
        #pragma unroll
        for (int off = 4; off > 0; off >>= 1)
            val += __shfl_down_sync(0xffffffffu, val, off);
        if (lane == 0) atomicAdd(out, val);
    }
}

extern "C" void kernel_launch(void* const* d_in, const int* in_sizes, int n_in,
                              void* d_out, int out_size) {
    const float* inp = (const float*)d_in[0];
    const float* tgt = (const float*)d_in[1];
    float* out = (float*)d_out;

    sx_zero_kernel<<<1, 32>>>(out);
    stixel_kernel<<<NBC, 256>>>(inp, tgt, out);
}

// round 4
// speedup vs baseline: 1.2693x; 1.2031x over previous
#include <cuda_runtime.h>
#include <cuda_bf16.h>

// StixelLoss fused kernel: float2 loads, register double-buffer pipeline,
// 512-thread blocks (4 H-segments), shared-memory dense-scan stitch.
// inputs:  (B=256, C=2, H=192, W=256) f32
// targets: (1, B, C, H, W) f32 (same layout after squeeze)
// out:     scalar f32 = ALPHA*bce_mean + BETA*cuts + GAMMA*dense

#define HH   192
#define WW   256
#define NBC  512            // B*C blocks
#define NP   (WW / 2)       // 128 float2 pairs per row
#define NSEG 4
#define SEGH (HH / NSEG)    // 48

__global__ void sx_zero_kernel(float* out) {
    if (threadIdx.x == 0) out[0] = 0.0f;
}

__device__ __forceinline__ float bce_term(float p, float t) {
    float lp  = fmaxf(__logf(p), -100.0f);
    float l1p = fmaxf(__logf(1.0f - p), -100.0f);
    return fmaf(t, lp - l1p, l1p);
}

__global__ __launch_bounds__(512)
void stixel_kernel(const float* __restrict__ inp,
                   const float* __restrict__ tgt,
                   float* __restrict__ out) {
    const int bc = blockIdx.x;               // b*2 + c
    const int c  = bc & 1;
    const int q  = threadIdx.x & (NP - 1);   // column pair (cols 2q, 2q+1)
    const int s  = threadIdx.x >> 7;         // h-segment 0..3
    const int h0 = s * SEGH;

    const size_t base = (size_t)bc * (HH * WW) + (size_t)h0 * WW + 2 * q;
    const float2* ip2 = (const float2*)(inp + base);
    const float2* tp2 = (const float2*)(tgt + base);

    float bce   = 0.0f;
    float dense = 0.0f;
    int   cuts  = 0;

    __shared__ int   s_last[NSEG][WW];
    __shared__ float sred[16];

    if (c == 0) {
        // channel 0: BCE + cuts, software-pipelined loads
        float2 pc = ip2[0];
        float2 tc = tp2[0];
        #pragma unroll 4
        for (int i = 0; i < SEGH - 1; ++i) {
            float2 pn = ip2[(i + 1) * NP];    // prefetch next row
            float2 tn = tp2[(i + 1) * NP];
            bce += bce_term(pc.x, tc.x) + bce_term(pc.y, tc.y);
            cuts += (pc.x > 0.5f) ? 1 : 0;
            cuts += (pc.y > 0.5f) ? 1 : 0;
            pc = pn; tc = tn;
        }
        bce += bce_term(pc.x, tc.x) + bce_term(pc.y, tc.y);
        cuts += (pc.x > 0.5f) ? 1 : 0;
        cuts += (pc.y > 0.5f) ? 1 : 0;
        __syncthreads();   // keep block convergent with channel-1 path
    } else {
        // channel 1: BCE + segmented dense scan over 2 columns.
        // prev==0 encodes "no visible predecessor" (a hit at global h=0 sets
        // prev=0, which the reference's prev!=0 check also ignores).
        int prev0 = 0, prev1 = 0;
        int fh0 = -1, fh1 = -1;
        float2 pc = ip2[0];
        float2 tc = tp2[0];
        #pragma unroll 4
        for (int i = 0; i < SEGH; ++i) {
            float2 pn, tn;
            if (i < SEGH - 1) { pn = ip2[(i + 1) * NP]; tn = tp2[(i + 1) * NP]; }
            const int h = h0 + i;
            bce += bce_term(pc.x, tc.x) + bce_term(pc.y, tc.y);
            bool m0 = (pc.x > 0.5f) && (h < HH - 1);   // dense excludes h=191
            bool m1 = (pc.y > 0.5f) && (h < HH - 1);
            if (m0) {
                if (prev0 != 0) {
                    float d = (float)(h - prev0);
                    dense += __fdividef(1.0f, d * d * d);
                }
                if (fh0 < 0) fh0 = h;
                prev0 = h;
            }
            if (m1) {
                if (prev1 != 0) {
                    float d = (float)(h - prev1);
                    dense += __fdividef(1.0f, d * d * d);
                }
                if (fh1 < 0) fh1 = h;
                prev1 = h;
            }
            pc = pn; tc = tn;
        }
        // publish last hit per column (0 = none / invisible)
        s_last[s][2 * q]     = prev0;
        s_last[s][2 * q + 1] = prev1;
        __syncthreads();
        // stitch cross-boundary contribution of this segment's first hits
        if (s > 0) {
            if (fh0 >= 0) {
                int pg = 0;
                for (int k = s - 1; k >= 0; --k) {
                    int lh = s_last[k][2 * q];
                    if (lh != 0) { pg = lh; break; }
                }
                if (pg != 0) {
                    float d = (float)(fh0 - pg);
                    dense += __fdividef(1.0f, d * d * d);
                }
            }
            if (fh1 >= 0) {
                int pg = 0;
                for (int k = s - 1; k >= 0; --k) {
                    int lh = s_last[k][2 * q + 1];
                    if (lh != 0) { pg = lh; break; }
                }
                if (pg != 0) {
                    float d = (float)(fh1 - pg);
                    dense += __fdividef(1.0f, d * d * d);
                }
            }
        }
    }

    // combine per-thread terms (ALPHA=1, BETA=0.001, GAMMA=0.1)
    const float INV_N = 1.0f / (float)((size_t)NBC * HH * WW);
    float val = -bce * INV_N + 0.001f * (float)cuts + 0.1f * dense;

    // block reduction over 512 threads
    #pragma unroll
    for (int off = 16; off > 0; off >>= 1)
        val += __shfl_down_sync(0xffffffffu, val, off);
    int lane = threadIdx.x & 31;
    int wid  = threadIdx.x >> 5;
    if (lane == 0) sred[wid] = val;
    __syncthreads();
    if (wid == 0) {
        val = (lane < 16) ? sred[lane] : 0.0f;
        #pragma unroll
        for (int off = 8; off > 0; off >>= 1)
            val += __shfl_down_sync(0xffffffffu, val, off);
        if (lane == 0) atomicAdd(out, val);
    }
}

extern "C" void kernel_launch(void* const* d_in, const int* in_sizes, int n_in,
                              void* d_out, int out_size) {
    const float* inp = (const float*)d_in[0];
    const float* tgt = (const float*)d_in[1];
    float* out = (float*)d_out;

    sx_zero_kernel<<<1, 32>>>(out);
    stixel_kernel<<<NBC, 512>>>(inp, tgt, out);
}

// round 5
// speedup vs baseline: 1.4396x; 1.1341x over previous
#include <cuda_runtime.h>
#include <cuda_bf16.h>

// StixelLoss fused kernel v5: bitmask dense scan + log2 BCE, no clamps.
// inputs:  (B=256, C=2, H=192, W=256) f32, values in (1e-4, 1-1e-4)
// targets: (1, B, C, H, W) f32
// out:     scalar f32 = ALPHA*bce_mean + BETA*cuts + GAMMA*dense

#define HH    192
#define WW    256
#define NBC   512           // B*C blocks
#define NQ    64            // float4 quads per row
#define NSEG  8             // 24-row segments
#define SEGH  24
#define TABN  1216          // covers d + sentinel offset
#define SENT  (-1000)       // prev sentinel: idx = pos+1000 in [1001,1190] -> tab 0

__global__ void sx_zero_kernel(float* out) {
    if (threadIdx.x == 0) out[0] = 0.0f;
}

__global__ __launch_bounds__(512, 4)
void stixel_kernel(const float* __restrict__ inp,
                   const float* __restrict__ tgt,
                   float* __restrict__ out) {
    const int bc = blockIdx.x;            // b*2 + c
    const int c  = bc & 1;
    const int q  = threadIdx.x & (NQ - 1);   // column quad (cols 4q..4q+3)
    const int s  = threadIdx.x >> 6;          // h-segment 0..7
    const int h0 = s * SEGH;

    __shared__ float        tab[TABN];
    __shared__ unsigned int smask[NSEG][WW];
    __shared__ float        sred[16];

    // channel 1 blocks: fill 1/d^3 table (zero outside [1,190])
    if (c == 1) {
        for (int k = threadIdx.x; k < TABN; k += 512) {
            float fd = (float)k;
            tab[k] = (k >= 1 && k < HH - 1) ? (1.0f / (fd * fd * fd)) : 0.0f;
        }
    }

    const size_t base = (size_t)bc * (HH * WW) + (size_t)h0 * WW + 4 * q;
    const float4* ip4 = (const float4*)(inp + base);
    const float4* tp4 = (const float4*)(tgt + base);

    float bce = 0.0f;
    unsigned int m0 = 0, m1 = 0, m2 = 0, m3 = 0;

    // hot loop: identical for both channels. BCE in log2 domain, mask build.
    #pragma unroll
    for (int i = 0; i < SEGH; ++i) {
        float4 p = ip4[i * NQ];
        float4 t = tp4[i * NQ];
        {
            float lp = __log2f(p.x), l1p = __log2f(1.0f - p.x);
            bce += l1p + t.x * (lp - l1p);
            if (p.x > 0.5f) m0 |= (1u << i);
        }
        {
            float lp = __log2f(p.y), l1p = __log2f(1.0f - p.y);
            bce += l1p + t.y * (lp - l1p);
            if (p.y > 0.5f) m1 |= (1u << i);
        }
        {
            float lp = __log2f(p.z), l1p = __log2f(1.0f - p.z);
            bce += l1p + t.z * (lp - l1p);
            if (p.z > 0.5f) m2 |= (1u << i);
        }
        {
            float lp = __log2f(p.w), l1p = __log2f(1.0f - p.w);
            bce += l1p + t.w * (lp - l1p);
            if (p.w > 0.5f) m3 |= (1u << i);
        }
    }

    float dense = 0.0f;
    int   cuts  = 0;

    if (c == 0) {
        // cuts = count of (p > 0.5) over all rows of channel 0
        cuts = __popc(m0) + __popc(m1) + __popc(m2) + __popc(m3);
    } else {
        // publish masks, then bit-scan half-columns
        smask[s][4 * q + 0] = m0;
        smask[s][4 * q + 1] = m1;
        smask[s][4 * q + 2] = m2;
        smask[s][4 * q + 3] = m3;
        __syncthreads();

        const int col  = threadIdx.x & (WW - 1);
        const int half = threadIdx.x >> 8;       // 0: rows 0..95, 1: rows 96..191

        int prev = SENT;
        if (half == 1) {
            // initial prev = last hit in rows 0..95 (bit 0 of seg0 is invisible)
            unsigned int u3 = smask[3][col];
            unsigned int u2 = smask[2][col];
            unsigned int u1 = smask[1][col];
            unsigned int u0 = smask[0][col] & ~1u;
            if      (u3) prev = 72 + 31 - __clz(u3);
            else if (u2) prev = 48 + 31 - __clz(u2);
            else if (u1) prev = 24 + 31 - __clz(u1);
            else if (u0) prev =      31 - __clz(u0);
        }

        #pragma unroll
        for (int k = 0; k < 4; ++k) {
            unsigned int w = smask[half * 4 + k][col];
            if (half == 0 && k == 0) w &= ~1u;             // hit at h=0 invisible
            if (half == 1 && k == 3) w &= ~(1u << 23);     // h=191 excluded
            const int rowbase = (half * 4 + k) * SEGH;
            while (w) {
                int b = __ffs(w) - 1;
                w &= (w - 1);
                int pos = rowbase + b;
                dense += tab[pos - prev];   // tab==0 when prev is sentinel
                prev = pos;
            }
        }
    }

    // combine per-thread terms (ALPHA=1, BETA=0.001, GAMMA=0.1)
    // bce is in log2 units; scale by ln2/N and negate.
    const float SCALE_BCE = -0.69314718055994531f /
                            (float)((size_t)NBC * HH * WW);
    float val = bce * SCALE_BCE + 0.001f * (float)cuts + 0.1f * dense;

    // block reduction over 512 threads
    #pragma unroll
    for (int off = 16; off > 0; off >>= 1)
        val += __shfl_down_sync(0xffffffffu, val, off);
    int lane = threadIdx.x & 31;
    int wid  = threadIdx.x >> 5;
    if (lane == 0) sred[wid] = val;
    __syncthreads();
    if (wid == 0) {
        val = (lane < 16) ? sred[lane] : 0.0f;
        #pragma unroll
        for (int off = 8; off > 0; off >>= 1)
            val += __shfl_down_sync(0xffffffffu, val, off);
        if (lane == 0) atomicAdd(out, val);
    }
}

extern "C" void kernel_launch(void* const* d_in, const int* in_sizes, int n_in,
                              void* d_out, int out_size) {
    const float* inp = (const float*)d_in[0];
    const float* tgt = (const float*)d_in[1];
    float* out = (float*)d_out;

    sx_zero_kernel<<<1, 32>>>(out);
    stixel_kernel<<<NBC, 512>>>(inp, tgt, out);
}